// round 8
// baseline (speedup 1.0000x reference)
#include <cuda_runtime.h>
#include <math.h>

#define NB 64
#define NG 32
#define TOT 64512          // 49152 + 12288 + 3072
#define NTASK 192          // 64 images x 3 scales
#define HB 4096            // 12-bit histogram
#define MAXN 49152

__device__ double   g_acc;                         // zeroed by k_fin after read
__device__ int      g_numpos[NTASK];               // zeroed by k_plan after read
__device__ unsigned g_negmask[(size_t)NB * TOT / 32];
__device__ unsigned g_hist[NTASK * HB];            // zeroed by k_plan after read
__device__ unsigned g_bufcnt[NTASK];               // zeroed by k_refine after read
__device__ unsigned g_buf[(size_t)NTASK * MAXN];
__device__ int      g_planT[NTASK];
__device__ int      g_planKK[NTASK];

__device__ __forceinline__ float sl1(float x) {
    float ax = fabsf(x);
    return (ax < 1.0f) ? 0.5f * x * x : ax - 0.5f;
}
__device__ __forceinline__ float softplus0(float x) {
    return fmaxf(x, 0.0f) + log1pf(expf(-fabsf(x)));
}
// float -> order-preserving key (descending float == descending uint)
__device__ __forceinline__ unsigned f2u(float f) {
    unsigned u = __float_as_uint(f);
    return (u & 0x80000000u) ? ~u : (u | 0x80000000u);
}
__device__ __forceinline__ float key2f(unsigned k) {
    unsigned u = (k & 0x80000000u) ? (k & 0x7FFFFFFFu) : ~k;
    return __uint_as_float(u);
}
__device__ __forceinline__ void task_dims(int s, int& N, int& off) {
    N   = (s == 0) ? 49152 : ((s == 1) ? 12288 : 3072);
    off = (s == 0) ? 0     : ((s == 1) ? 49152 : 61440);
}

// exclusive prefix over the block's 256 threads (warp shuffles, 2 barriers)
__device__ __forceinline__ int scan256(int v) {
    __shared__ int wsum[8];
    const int lane = threadIdx.x & 31, wid = threadIdx.x >> 5;
    int inc = v;
    #pragma unroll
    for (int o = 1; o < 32; o <<= 1) {
        int t = __shfl_up_sync(0xFFFFFFFFu, inc, o);
        if (lane >= o) inc += t;
    }
    __syncthreads();
    if (lane == 31) wsum[wid] = inc;
    __syncthreads();
    int woff = 0;
    #pragma unroll
    for (int i = 0; i < 8; ++i) if (i < wid) woff += wsum[i];
    return woff + inc - v;
}

__device__ __forceinline__ float block_reduce(float v, float* rs) {
    #pragma unroll
    for (int o = 16; o; o >>= 1) v += __shfl_down_sync(0xFFFFFFFFu, v, o);
    const int wid = threadIdx.x >> 5, lid = threadIdx.x & 31;
    if (lid == 0) rs[wid] = v;
    __syncthreads();
    float tot = 0.0f;
    if (threadIdx.x == 0) {
        #pragma unroll
        for (int i = 0; i < 8; ++i) tot += rs[i];
    }
    return tot;
}

// ---------------------------------------------------------------------------
// Pass 1: 32x8-pixel tiles, spatial GT culling, losses, fused histogram,
// neg-bit mask via warp ballot (warp = 32 consecutive p -> aligned words).
// ---------------------------------------------------------------------------
__global__ __launch_bounds__(256) void k_assign(
    const float* __restrict__ pred0,
    const float* __restrict__ pred1,
    const float* __restrict__ pred2,
    const float* __restrict__ gt_boxes,
    const int*   __restrict__ gt_labels)
{
    const int b   = blockIdx.y;
    const int cx_ = blockIdx.x;            // 0..83
    const int tid = threadIdx.x;

    int scale, blkbase, W, HW, keyoff, TW;
    float stride;
    const float* pred;
    if (cx_ < 64)      { scale = 0; blkbase = 0;  W = 128; HW = 16384; stride = 8.0f;  keyoff = 0;     pred = pred0; TW = 4; }
    else if (cx_ < 80) { scale = 1; blkbase = 64; W = 64;  HW = 4096;  stride = 16.0f; keyoff = 49152; pred = pred1; TW = 2; }
    else               { scale = 2; blkbase = 80; W = 32;  HW = 1024;  stride = 32.0f; keyoff = 61440; pred = pred2; TW = 1; }

    const int tile = cx_ - blkbase;
    const int tbx = tile % TW, tby = tile / TW;   // 32-wide x 8-tall tiles
    const int tx = tid & 31, ty = tid >> 5;
    const int w = tbx * 32 + tx;
    const int h = tby * 8 + ty;
    const int p = h * W + w;

    __shared__ float4   s_cbox[NG];
    __shared__ float    s_carea[NG];
    __shared__ int      s_clbl[NG];
    __shared__ int      s_cnt;
    __shared__ unsigned sh_hist[HB];
    __shared__ float    rs[8];
    __shared__ int      rc[8];

    for (int i = tid; i < HB; i += 256) sh_hist[i] = 0;

    // warp 0: cull GTs vs tile anchor-reach bbox (exact: culled GTs have inter==0)
    if (tid < 32) {
        float4 g = ((const float4*)gt_boxes)[b * NG + tid];
        float rx0 = ((float)(tbx * 32) - 2.0f) * stride;
        float rx1 = ((float)(tbx * 32) + 34.0f) * stride;
        float ry0 = ((float)(tby * 8) - 2.0f) * stride;
        float ry1 = ((float)(tby * 8) + 10.0f) * stride;
        bool c = (g.x <= rx1) && (g.z >= rx0) && (g.y <= ry1) && (g.w >= ry0);
        unsigned m = __ballot_sync(0xFFFFFFFFu, c);
        if (c) {
            int pos = __popc(m & ((1u << tid) - 1u));
            s_cbox[pos]  = g;
            s_carea[pos] = (g.z - g.x) * (g.w - g.y);
            s_clbl[pos]  = gt_labels[b * NG + tid];
        }
        if (tid == 0) s_cnt = __popc(m);
    }
    __syncthreads();
    const int cnt = s_cnt;

    float loss = 0.0f;
    int   cpos = 0;
    const float cxp = (w + 0.5f) * stride;
    const float cyp = (h + 0.5f) * stride;
    const int lane = tid & 31;

    #pragma unroll
    for (int a = 0; a < 3; ++a) {
        const float s   = (float)(3 + a) * stride;
        const float hlf = 0.5f * s;
        const float ax1 = cxp - hlf, ay1 = cyp - hlf;
        const float ax2 = cxp + hlf, ay2 = cyp + hlf;
        const float areaA = s * s;

        // division-free argmax over surviving GTs (first-max tie-break preserved)
        float BI = 0.0f, BS = 1.0f; int BX = 0;
        for (int j = 0; j < cnt; ++j) {
            float4 g = s_cbox[j];
            float lx = fmaxf(ax1, g.x), ly = fmaxf(ay1, g.y);
            float rx = fminf(ax2, g.z), ry = fminf(ay2, g.w);
            float iw = fmaxf(rx - lx, 0.0f), ih = fmaxf(ry - ly, 0.0f);
            float inter = iw * ih;
            float S     = areaA + s_carea[j];
            if (inter * BS > BI * S) { BI = inter; BS = S; BX = j; }
        }

        const float denom    = (BS - BI) + 1e-9f;
        const float best_iou = BI / denom;
        const bool  pos = (best_iou >= 0.5f);
        const bool  neg = (best_iou <  0.4f);

        const size_t base = ((size_t)b * 24 + a * 8) * (size_t)HW + p;
        const float  xo   = pred[base + 4 * (size_t)HW];
        const float  key  = neg ? xo : -1e30f;
        atomicAdd(&sh_hist[f2u(key) >> 20], 1u);

        // packed neg mask: warp covers 32 consecutive p, same plane
        unsigned mword = __ballot_sync(0xFFFFFFFFu, neg);
        if (lane == 0)
            g_negmask[((size_t)b * TOT + keyoff + (size_t)a * HW + p) >> 5] = mword;

        if (pos) {
            cpos++;
            loss += fmaxf(xo, 0.0f) - xo + log1pf(expf(-fabsf(xo)));

            float4 g = s_cbox[BX];
            float gx = (g.x + g.z) * 0.5f;
            float gy = (g.y + g.w) * 0.5f;
            float gw = fmaxf(g.z - g.x, 1e-6f);
            float gh = fmaxf(g.w - g.y, 1e-6f);
            float aw = fmaxf(ax2 - ax1, 1e-6f);
            float ah = fmaxf(ay2 - ay1, 1e-6f);

            float ttx = (gx - cxp) / aw;
            float tty = (gy - cyp) / ah;
            float ttw = logf(gw / aw);
            float tth = logf(gh / ah);

            float p0 = pred[base];
            float p1 = pred[base + 1 * (size_t)HW];
            float p2 = pred[base + 2 * (size_t)HW];
            float p3 = pred[base + 3 * (size_t)HW];
            loss += sl1(p0 - ttx) + sl1(p1 - tty) + sl1(p2 - ttw) + sl1(p3 - tth);

            float c0 = pred[base + 5 * (size_t)HW];
            float c1 = pred[base + 6 * (size_t)HW];
            float c2 = pred[base + 7 * (size_t)HW];
            float m  = fmaxf(c0, fmaxf(c1, c2));
            float lse = m + logf(expf(c0 - m) + expf(c1 - m) + expf(c2 - m));
            int   t   = max(s_clbl[BX], 0);
            float pt  = (t == 0) ? c0 : ((t == 1) ? c1 : c2);
            loss += lse - pt;
        }
    }

    #pragma unroll
    for (int o = 16; o; o >>= 1) {
        loss += __shfl_down_sync(0xFFFFFFFFu, loss, o);
        cpos += __shfl_down_sync(0xFFFFFFFFu, cpos, o);
    }
    const int wid = tid >> 5;
    if (lane == 0) { rs[wid] = loss; rc[wid] = cpos; }
    __syncthreads();
    if (tid == 0) {
        float L = 0.0f; int C = 0;
        #pragma unroll
        for (int i = 0; i < 8; ++i) { L += rs[i]; C += rc[i]; }
        if (L != 0.0f) atomicAdd(&g_acc, (double)L);
        if (C)         atomicAdd(&g_numpos[b * 3 + scale], C);
    }

    unsigned* gh = g_hist + (b * 3 + scale) * HB;
    for (int i = tid; i < HB; i += 256) {
        unsigned c = sh_hist[i];
        if (c) atomicAdd(&gh[i], c);
    }
}

// ---------------------------------------------------------------------------
// S2: per-task descending histogram scan -> threshold bin + kk.
// Restores g_hist and g_numpos to zero for the next graph replay.
// ---------------------------------------------------------------------------
__global__ __launch_bounds__(256) void k_plan() {
    const int task = blockIdx.x;
    const int s = task % 3;
    int N, off; task_dims(s, N, off);

    int np = g_numpos[task];
    int k = 3 * max(1, np);
    if (k > N) k = N;

    unsigned* gh = g_hist + task * HB;
    int cnt[16], tot = 0;
    #pragma unroll
    for (int i = 0; i < 16; ++i) {
        int bin = HB - 1 - (threadIdx.x * 16 + i);
        cnt[i] = (int)gh[bin];
        tot += cnt[i];
    }
    int excl = scan256(tot);
    if (excl < k && excl + tot >= k) {
        int cum = excl;
        #pragma unroll
        for (int i = 0; i < 16; ++i) {
            if (cum + cnt[i] >= k) {
                g_planT[task]  = HB - 1 - (threadIdx.x * 16 + i);
                g_planKK[task] = k - cum;
                break;
            }
            cum += cnt[i];
        }
    }
    // restore zeros
    #pragma unroll
    for (int i = 0; i < 16; ++i) gh[HB - 1 - (threadIdx.x * 16 + i)] = 0;
    if (threadIdx.x == 0) g_numpos[task] = 0;
}

// ---------------------------------------------------------------------------
// S3: reconstruct keys from pred obj plane (L2-resident) + neg mask;
// sum softplus above threshold bin; compact tie-bin members. grid=(12,NTASK)
// ---------------------------------------------------------------------------
__global__ __launch_bounds__(256) void k_sumgather(
    const float* __restrict__ pred0,
    const float* __restrict__ pred1,
    const float* __restrict__ pred2)
{
    __shared__ float rs[8];
    const int task = blockIdx.y;
    const int s = task % 3, b = task / 3;
    int N, off; task_dims(s, N, off);
    const int n4 = N >> 2;
    const int base4 = blockIdx.x * 1024;
    if (base4 >= n4) return;

    const int HW      = (s == 0) ? 16384 : ((s == 1) ? 4096 : 1024);
    const int hwsh    = (s == 0) ? 14 : ((s == 1) ? 12 : 10);
    const float* pred = (s == 0) ? pred0 : ((s == 1) ? pred1 : pred2);
    const float* po   = pred + ((size_t)b * 24 + 4) * (size_t)HW;  // obj plane base
    const unsigned* mk = g_negmask + (((size_t)b * TOT + off) >> 5);

    const unsigned T = (unsigned)g_planT[task];
    const unsigned NEGKEY0 = f2u(-1e30f);
    unsigned* buf = g_buf + (size_t)task * MAXN;

    // batch loads for MLP
    float4   v[4];
    unsigned mw[4];
    int      e4a[4];
    bool     ok[4];
    #pragma unroll
    for (int k = 0; k < 4; ++k) {
        int i4 = base4 + threadIdx.x + k * 256;
        ok[k] = (i4 < n4);
        if (ok[k]) {
            int e4 = i4 << 2;
            int a  = e4 >> hwsh;
            int pp = e4 & (HW - 1);
            v[k]  = *(const float4*)(po + (size_t)a * 8 * HW + pp);
            mw[k] = mk[i4 >> 3];
            e4a[k] = e4;
        }
    }

    float local = 0.0f;
    #pragma unroll
    for (int k = 0; k < 4; ++k) {
        if (!ok[k]) continue;
        unsigned bits = (mw[k] >> (e4a[k] & 31)) & 0xFu;
        float xs[4] = {v[k].x, v[k].y, v[k].z, v[k].w};
        #pragma unroll
        for (int q = 0; q < 4; ++q) {
            unsigned u = (bits >> q & 1u) ? f2u(xs[q]) : NEGKEY0;
            unsigned bin = u >> 20;
            if (bin > T)       local += softplus0(key2f(u));
            else if (bin == T) buf[atomicAdd(&g_bufcnt[task], 1u)] = u;
        }
    }
    float tot = block_reduce(local, rs);
    if (threadIdx.x == 0 && tot != 0.0f) atomicAdd(&g_acc, (double)tot);
}

// ---------------------------------------------------------------------------
// S4: per-task exact refinement over tie-bin members (mid 12 + low 8 bits).
// Restores g_bufcnt to zero.
// ---------------------------------------------------------------------------
__global__ __launch_bounds__(256) void k_refine() {
    __shared__ unsigned h2[HB];
    __shared__ unsigned h3[256];
    __shared__ float    rs[8];
    __shared__ int      sT2, sKK2, sT3, sKK3;

    const int task = blockIdx.x;
    const int m  = (int)g_bufcnt[task];
    const int kk = g_planKK[task];
    const unsigned top12 = (unsigned)g_planT[task];
    const unsigned* buf = g_buf + (size_t)task * MAXN;

    for (int i = threadIdx.x; i < HB; i += 256) h2[i] = 0;
    h3[threadIdx.x] = 0;
    __syncthreads();

    for (int i = threadIdx.x; i < m; i += 256)
        atomicAdd(&h2[(buf[i] >> 8) & 0xFFFu], 1u);
    __syncthreads();

    {
        int cnt[16], tot = 0;
        #pragma unroll
        for (int i = 0; i < 16; ++i) {
            int bin = HB - 1 - (threadIdx.x * 16 + i);
            cnt[i] = (int)h2[bin];
            tot += cnt[i];
        }
        int excl = scan256(tot);
        if (excl < kk && excl + tot >= kk) {
            int cum = excl;
            #pragma unroll
            for (int i = 0; i < 16; ++i) {
                if (cum + cnt[i] >= kk) { sT2 = HB - 1 - (threadIdx.x * 16 + i); sKK2 = kk - cum; break; }
                cum += cnt[i];
            }
        }
    }
    __syncthreads();
    const unsigned T2 = (unsigned)sT2;
    const int kk2 = sKK2;

    float local = 0.0f;
    for (int i = threadIdx.x; i < m; i += 256) {
        unsigned u = buf[i];
        unsigned mid = (u >> 8) & 0xFFFu;
        if (mid > T2)       local += softplus0(key2f(u));
        else if (mid == T2) atomicAdd(&h3[u & 0xFFu], 1u);
    }
    __syncthreads();

    {
        int bin = 255 - threadIdx.x;
        int c = (int)h3[bin];
        int excl = scan256(c);
        if (excl < kk2 && excl + c >= kk2) { sT3 = bin; sKK3 = kk2 - excl; }
    }
    __syncthreads();
    const unsigned T3 = (unsigned)sT3;
    const int kk3 = sKK3;
    const unsigned ustar = (top12 << 20) | (T2 << 8) | T3;

    for (int i = threadIdx.x; i < m; i += 256) {
        unsigned u = buf[i];
        if (((u >> 8) & 0xFFFu) == T2 && (u & 0xFFu) > T3)
            local += softplus0(key2f(u));
    }
    __syncthreads();
    float tot = block_reduce(local, rs);
    if (threadIdx.x == 0) {
        tot += (float)kk3 * softplus0(key2f(ustar));
        atomicAdd(&g_acc, (double)tot);
        g_bufcnt[task] = 0;   // restore zero for next replay
    }
}

__global__ void k_fin(float* out) {
    out[0] = (float)(g_acc * (1.0 / 64.0));
    g_acc = 0.0;              // restore zero for next replay
}

extern "C" void kernel_launch(void* const* d_in, const int* in_sizes, int n_in,
                              void* d_out, int out_size)
{
    const float* pred0 = (const float*)d_in[0];
    const float* pred1 = (const float*)d_in[2];
    const float* pred2 = (const float*)d_in[4];
    const float* gtb   = (const float*)d_in[6];
    const int*   gtl   = (const int*)d_in[7];

    dim3 ga(84, NB);
    k_assign<<<ga, 256>>>(pred0, pred1, pred2, gtb, gtl);

    k_plan<<<NTASK, 256>>>();
    dim3 gh(12, NTASK);
    k_sumgather<<<gh, 256>>>(pred0, pred1, pred2);
    k_refine<<<NTASK, 256>>>();
    k_fin<<<1, 1>>>((float*)d_out);
}

// round 11
// speedup vs baseline: 1.0952x; 1.0952x over previous
#include <cuda_runtime.h>
#include <math.h>

#define NB 64
#define NG 32
#define TOT 64512          // 49152 + 12288 + 3072
#define NTASK 192          // 64 images x 3 scales
#define HB 4096            // 12-bit histogram
#define MAXN 49152
#define SH_CAP 4096        // shared tie-buffer capacity

__device__ double   g_acc;                 // zeroed by k_fin after read
__device__ int      g_numpos[NTASK];       // zeroed by k_select after read
__device__ float    g_keys[(size_t)NB * TOT];
__device__ unsigned g_hist[NTASK * HB];    // zeroed by k_select after read
__device__ unsigned g_buf[(size_t)NTASK * MAXN];  // overflow only (rare)

__device__ __forceinline__ float sl1(float x) {
    float ax = fabsf(x);
    return (ax < 1.0f) ? 0.5f * x * x : ax - 0.5f;
}
__device__ __forceinline__ float softplus0(float x) {
    return fmaxf(x, 0.0f) + log1pf(expf(-fabsf(x)));
}
// float -> order-preserving key (descending float == descending uint)
__device__ __forceinline__ unsigned f2u(float f) {
    unsigned u = __float_as_uint(f);
    return (u & 0x80000000u) ? ~u : (u | 0x80000000u);
}
__device__ __forceinline__ float key2f(unsigned k) {
    unsigned u = (k & 0x80000000u) ? (k & 0x7FFFFFFFu) : ~k;
    return __uint_as_float(u);
}

// exclusive prefix over 1024 threads (warp shuffles, 3 barriers)
__device__ __forceinline__ int scan1024(int v) {
    __shared__ int wsum[32];
    const int lane = threadIdx.x & 31, wid = threadIdx.x >> 5;
    int inc = v;
    #pragma unroll
    for (int o = 1; o < 32; o <<= 1) {
        int t = __shfl_up_sync(0xFFFFFFFFu, inc, o);
        if (lane >= o) inc += t;
    }
    __syncthreads();               // protect wsum reuse across calls
    if (lane == 31) wsum[wid] = inc;
    __syncthreads();
    if (wid == 0) {
        int w = wsum[lane];
        int winc = w;
        #pragma unroll
        for (int o = 1; o < 32; o <<= 1) {
            int t = __shfl_up_sync(0xFFFFFFFFu, winc, o);
            if (lane >= o) winc += t;
        }
        wsum[lane] = winc - w;     // exclusive warp offsets
    }
    __syncthreads();
    return wsum[wid] + inc - v;
}

// ---------------------------------------------------------------------------
// Pass 1: 32x16-pixel tiles (512 thr), spatial GT culling, losses,
// fused per-task 4096-bin histogram, key scatter.
// ---------------------------------------------------------------------------
__global__ __launch_bounds__(512) void k_assign(
    const float* __restrict__ pred0,
    const float* __restrict__ pred1,
    const float* __restrict__ pred2,
    const float* __restrict__ gt_boxes,
    const int*   __restrict__ gt_labels)
{
    const int b   = blockIdx.y;
    const int cx_ = blockIdx.x;            // 0..41
    const int tid = threadIdx.x;

    int scale, blkbase, W, HW, keyoff, TW;
    float stride;
    const float* pred;
    if (cx_ < 32)      { scale = 0; blkbase = 0;  W = 128; HW = 16384; stride = 8.0f;  keyoff = 0;     pred = pred0; TW = 4; }
    else if (cx_ < 40) { scale = 1; blkbase = 32; W = 64;  HW = 4096;  stride = 16.0f; keyoff = 49152; pred = pred1; TW = 2; }
    else               { scale = 2; blkbase = 40; W = 32;  HW = 1024;  stride = 32.0f; keyoff = 61440; pred = pred2; TW = 1; }

    const int tile = cx_ - blkbase;
    const int tbx = tile % TW, tby = tile / TW;   // 32-wide x 16-tall tiles
    const int tx = tid & 31, ty = tid >> 5;
    const int w = tbx * 32 + tx;
    const int h = tby * 16 + ty;
    const int p = h * W + w;

    __shared__ float4   s_cbox[NG];
    __shared__ float    s_carea[NG];
    __shared__ int      s_clbl[NG];
    __shared__ int      s_cnt;
    __shared__ unsigned sh_hist[HB];
    __shared__ float    rs[16];
    __shared__ int      rc[16];

    for (int i = tid; i < HB; i += 512) sh_hist[i] = 0;

    // warp 0: cull GTs vs tile anchor-reach bbox (exact: culled GTs have inter==0
    // with every anchor in this tile, so they can never win the argmax; when all
    // IoUs are 0 the anchor is neg and best_idx is unused).
    if (tid < 32) {
        float4 g = ((const float4*)gt_boxes)[b * NG + tid];
        float rx0 = ((float)(tbx * 32) - 2.0f) * stride;
        float rx1 = ((float)(tbx * 32) + 34.0f) * stride;
        float ry0 = ((float)(tby * 16) - 2.0f) * stride;
        float ry1 = ((float)(tby * 16) + 18.0f) * stride;
        bool c = (g.x <= rx1) && (g.z >= rx0) && (g.y <= ry1) && (g.w >= ry0);
        unsigned m = __ballot_sync(0xFFFFFFFFu, c);
        if (c) {
            int pos = __popc(m & ((1u << tid) - 1u));
            s_cbox[pos]  = g;
            s_carea[pos] = (g.z - g.x) * (g.w - g.y);
            s_clbl[pos]  = gt_labels[b * NG + tid];
        }
        if (tid == 0) s_cnt = __popc(m);
    }
    __syncthreads();
    const int cnt = s_cnt;

    float loss = 0.0f;
    int   cpos = 0;
    const float cxp = (w + 0.5f) * stride;
    const float cyp = (h + 0.5f) * stride;
    float* keyb = g_keys + (size_t)b * TOT + keyoff;

    #pragma unroll
    for (int a = 0; a < 3; ++a) {
        const float s   = (float)(3 + a) * stride;
        const float hlf = 0.5f * s;
        const float ax1 = cxp - hlf, ay1 = cyp - hlf;
        const float ax2 = cxp + hlf, ay2 = cyp + hlf;
        const float areaA = s * s;

        // division-free argmax over surviving GTs (first-max tie-break preserved)
        float BI = 0.0f, BS = 1.0f; int BX = 0;
        for (int j = 0; j < cnt; ++j) {
            float4 g = s_cbox[j];
            float lx = fmaxf(ax1, g.x), ly = fmaxf(ay1, g.y);
            float rx = fminf(ax2, g.z), ry = fminf(ay2, g.w);
            float iw = fmaxf(rx - lx, 0.0f), ih = fmaxf(ry - ly, 0.0f);
            float inter = iw * ih;
            float S     = areaA + s_carea[j];
            if (inter * BS > BI * S) { BI = inter; BS = S; BX = j; }
        }

        const float denom    = (BS - BI) + 1e-9f;
        const float best_iou = BI / denom;
        const bool  pos = (best_iou >= 0.5f);
        const bool  neg = (best_iou <  0.4f);

        const size_t base = ((size_t)b * 24 + a * 8) * (size_t)HW + p;
        const float  xo   = pred[base + 4 * (size_t)HW];
        const float  key  = neg ? xo : -1e30f;
        keyb[a * HW + p] = key;
        atomicAdd(&sh_hist[f2u(key) >> 20], 1u);

        if (pos) {
            cpos++;
            loss += fmaxf(xo, 0.0f) - xo + log1pf(expf(-fabsf(xo)));

            float4 g = s_cbox[BX];
            float gx = (g.x + g.z) * 0.5f;
            float gy = (g.y + g.w) * 0.5f;
            float gw = fmaxf(g.z - g.x, 1e-6f);
            float gh = fmaxf(g.w - g.y, 1e-6f);
            float aw = fmaxf(ax2 - ax1, 1e-6f);
            float ah = fmaxf(ay2 - ay1, 1e-6f);

            float ttx = (gx - cxp) / aw;
            float tty = (gy - cyp) / ah;
            float ttw = logf(gw / aw);
            float tth = logf(gh / ah);

            float p0 = pred[base];
            float p1 = pred[base + 1 * (size_t)HW];
            float p2 = pred[base + 2 * (size_t)HW];
            float p3 = pred[base + 3 * (size_t)HW];
            loss += sl1(p0 - ttx) + sl1(p1 - tty) + sl1(p2 - ttw) + sl1(p3 - tth);

            float c0 = pred[base + 5 * (size_t)HW];
            float c1 = pred[base + 6 * (size_t)HW];
            float c2 = pred[base + 7 * (size_t)HW];
            float m  = fmaxf(c0, fmaxf(c1, c2));
            float lse = m + logf(expf(c0 - m) + expf(c1 - m) + expf(c2 - m));
            int   t   = max(s_clbl[BX], 0);
            float pt  = (t == 0) ? c0 : ((t == 1) ? c1 : c2);
            loss += lse - pt;
        }
    }

    #pragma unroll
    for (int o = 16; o; o >>= 1) {
        loss += __shfl_down_sync(0xFFFFFFFFu, loss, o);
        cpos += __shfl_down_sync(0xFFFFFFFFu, cpos, o);
    }
    const int wid = tid >> 5, lane = tid & 31;
    if (lane == 0) { rs[wid] = loss; rc[wid] = cpos; }
    __syncthreads();
    if (tid == 0) {
        float L = 0.0f; int C = 0;
        #pragma unroll
        for (int i = 0; i < 16; ++i) { L += rs[i]; C += rc[i]; }
        if (L != 0.0f) atomicAdd(&g_acc, (double)L);
        if (C)         atomicAdd(&g_numpos[b * 3 + scale], C);
    }

    unsigned* gh = g_hist + (b * 3 + scale) * HB;
    for (int i = tid; i < HB; i += 512) {
        unsigned c = sh_hist[i];
        if (c) atomicAdd(&gh[i], c);
    }
}

// ---------------------------------------------------------------------------
// Fused select: one block per task (1024 threads).
// Phase A: descending histogram scan -> threshold bin T + residual kk.
// Phase B: single pass over keys: sum softplus above T, compact ties to shared.
// Phase C: refine mid-12/low-8 bits over tie members -> exact top-k sum.
// Restores g_hist / g_numpos zeros for the next graph replay.
// ---------------------------------------------------------------------------
__global__ __launch_bounds__(1024) void k_select() {
    __shared__ unsigned s_tie[SH_CAP];
    __shared__ unsigned h2[HB];
    __shared__ unsigned h3[256];
    __shared__ int      s_tiecnt;
    __shared__ int      sT, sKK, sT2, sKK2, sT3, sKK3;
    __shared__ float    rs[32];

    const int task = blockIdx.x;
    const int s = task % 3, b = task / 3;
    const int N   = (s == 0) ? 49152 : ((s == 1) ? 12288 : 3072);
    const int off = (s == 0) ? 0     : ((s == 1) ? 49152 : 61440);
    const int tid = threadIdx.x;

    for (int i = tid; i < HB; i += 1024) h2[i] = 0;
    if (tid < 256) h3[tid] = 0;
    if (tid == 0) s_tiecnt = 0;

    int np = g_numpos[task];
    int k = 3 * max(1, np);
    if (k > N) k = N;

    // --- Phase A: plan over global histogram (4 bins/thread, descending) ---
    unsigned* gh = g_hist + task * HB;
    int cnt[4], tot = 0;
    #pragma unroll
    for (int i = 0; i < 4; ++i) {
        int bin = HB - 1 - (tid * 4 + i);
        cnt[i] = (int)gh[bin];
        gh[bin] = 0;                       // restore zero
        tot += cnt[i];
    }
    int excl = scan1024(tot);
    if (excl < k && excl + tot >= k) {
        int cum = excl;
        #pragma unroll
        for (int i = 0; i < 4; ++i) {
            if (cum + cnt[i] >= k) { sT = HB - 1 - (tid * 4 + i); sKK = k - cum; break; }
            cum += cnt[i];
        }
    }
    if (tid == 0) g_numpos[task] = 0;      // restore zero
    __syncthreads();
    const unsigned T = (unsigned)sT;
    const int kk = sKK;

    // --- Phase B: one pass over keys ---
    const uint4* keys4 = (const uint4*)(g_keys + (size_t)b * TOT + off);
    unsigned* obuf = g_buf + (size_t)task * MAXN;
    const int n4 = N >> 2;

    float local = 0.0f;
    for (int base4 = 0; base4 < n4; base4 += 4096) {
        uint4 v[4]; bool ok[4];
        #pragma unroll
        for (int q = 0; q < 4; ++q) {
            int i4 = base4 + tid + q * 1024;
            ok[q] = (i4 < n4);
            if (ok[q]) v[q] = keys4[i4];
        }
        #pragma unroll
        for (int q = 0; q < 4; ++q) {
            if (!ok[q]) continue;
            unsigned uu[4] = {f2u(__uint_as_float(v[q].x)), f2u(__uint_as_float(v[q].y)),
                              f2u(__uint_as_float(v[q].z)), f2u(__uint_as_float(v[q].w))};
            #pragma unroll
            for (int e = 0; e < 4; ++e) {
                unsigned bin = uu[e] >> 20;
                if (bin > T) local += softplus0(key2f(uu[e]));
                else if (bin == T) {
                    int idx = atomicAdd(&s_tiecnt, 1);
                    if (idx < SH_CAP) s_tie[idx] = uu[e];
                    else              obuf[idx - SH_CAP] = uu[e];
                }
            }
        }
    }
    __syncthreads();
    const int m = s_tiecnt;

    // --- Phase C1: histogram of mid-12 bits of ties ---
    for (int i = tid; i < m; i += 1024) {
        unsigned u = (i < SH_CAP) ? s_tie[i] : obuf[i - SH_CAP];
        atomicAdd(&h2[(u >> 8) & 0xFFFu], 1u);
    }
    __syncthreads();
    {
        int c2[4], t2 = 0;
        #pragma unroll
        for (int i = 0; i < 4; ++i) {
            int bin = HB - 1 - (tid * 4 + i);
            c2[i] = (int)h2[bin];
            t2 += c2[i];
        }
        int ex = scan1024(t2);
        if (ex < kk && ex + t2 >= kk) {
            int cum = ex;
            #pragma unroll
            for (int i = 0; i < 4; ++i) {
                if (cum + c2[i] >= kk) { sT2 = HB - 1 - (tid * 4 + i); sKK2 = kk - cum; break; }
                cum += c2[i];
            }
        }
    }
    __syncthreads();
    const unsigned T2 = (unsigned)sT2;
    const int kk2 = sKK2;

    // --- Phase C2: sum mid>T2; low-byte histogram for mid==T2 ---
    for (int i = tid; i < m; i += 1024) {
        unsigned u = (i < SH_CAP) ? s_tie[i] : obuf[i - SH_CAP];
        unsigned mid = (u >> 8) & 0xFFFu;
        if (mid > T2)       local += softplus0(key2f(u));
        else if (mid == T2) atomicAdd(&h3[u & 0xFFu], 1u);
    }
    __syncthreads();
    {
        int c3 = (tid < 256) ? (int)h3[255 - tid] : 0;
        int ex = scan1024(c3);
        if (tid < 256 && ex < kk2 && ex + c3 >= kk2) { sT3 = 255 - tid; sKK3 = kk2 - ex; }
    }
    __syncthreads();
    const unsigned T3 = (unsigned)sT3;
    const int kk3 = sKK3;
    const unsigned ustar = (T << 20) | (T2 << 8) | T3;

    // --- Phase C3: mid==T2 && low>T3 ---
    for (int i = tid; i < m; i += 1024) {
        unsigned u = (i < SH_CAP) ? s_tie[i] : obuf[i - SH_CAP];
        if (((u >> 8) & 0xFFFu) == T2 && (u & 0xFFu) > T3)
            local += softplus0(key2f(u));
    }

    // block reduction (32 warps)
    #pragma unroll
    for (int o = 16; o; o >>= 1) local += __shfl_down_sync(0xFFFFFFFFu, local, o);
    const int wid = tid >> 5, lane = tid & 31;
    if (lane == 0) rs[wid] = local;
    __syncthreads();
    if (tid == 0) {
        float tot2 = 0.0f;
        #pragma unroll
        for (int i = 0; i < 32; ++i) tot2 += rs[i];
        tot2 += (float)kk3 * softplus0(key2f(ustar));
        atomicAdd(&g_acc, (double)tot2);
    }
}

__global__ void k_fin(float* out) {
    out[0] = (float)(g_acc * (1.0 / 64.0));
    g_acc = 0.0;              // restore zero for next replay
}

extern "C" void kernel_launch(void* const* d_in, const int* in_sizes, int n_in,
                              void* d_out, int out_size)
{
    const float* pred0 = (const float*)d_in[0];
    const float* pred1 = (const float*)d_in[2];
    const float* pred2 = (const float*)d_in[4];
    const float* gtb   = (const float*)d_in[6];
    const int*   gtl   = (const int*)d_in[7];

    dim3 ga(42, NB);
    k_assign<<<ga, 512>>>(pred0, pred1, pred2, gtb, gtl);
    k_select<<<NTASK, 1024>>>();
    k_fin<<<1, 1>>>((float*)d_out);
}